// round 1
// baseline (speedup 1.0000x reference)
#include <cuda_runtime.h>
#include <cuda_bf16.h>
#include <math.h>

// ---------------- problem constants ----------------
#define BATCH 256
#define GENES 4000
#define PATH  128      // P
#define OMICS 3
#define DDIM  (OMICS * GENES)   // 12000
#define HDIM  64
#define ODIM  16
#define GHID  128      // gate hidden
#define CHID  8
#define NCLS  5
#define TOPK  3
#define BNEPS 1e-5f

// gate GEMM split-K config
#define KSPLIT 25
#define KC     160     // 25*160 = 4000
#define KB     16

// ---------------- device scratch (no allocations allowed) ----------------
__device__ float g_partial[KSPLIT * BATCH * GHID];   // split-K partials
__device__ float g_hidden[BATCH * GHID];
__device__ float g_logits[BATCH * PATH];
__device__ int   g_gene_idx[PATH * GENES];
__device__ int   g_gene_cnt[PATH];
__device__ int   g_path_cnt[PATH];
__device__ int   g_path_ent[PATH * BATCH];           // (b<<2)|k
__device__ float g_path_wt[PATH * BATCH];
__device__ float g_contrib[BATCH * TOPK * ODIM];

// ---------------- kernel 1: ordered gene-list compaction per pathway ----------------
__global__ void gene_list_kernel(const float* __restrict__ gene_mask) {
    int p = blockIdx.x;
    int tid = threadIdx.x;
    int wid = tid >> 5, lane = tid & 31;
    __shared__ int base;
    __shared__ int wcnt[8];
    __shared__ int woff[8];
    if (tid == 0) { base = 0; g_path_cnt[p] = 0; }
    __syncthreads();
    for (int g0 = 0; g0 < GENES; g0 += 256) {
        int g = g0 + tid;
        bool pred = (g < GENES) && (gene_mask[(size_t)g * PATH + p] != 0.0f);
        unsigned m = __ballot_sync(0xffffffffu, pred);
        if (lane == 0) wcnt[wid] = __popc(m);
        __syncthreads();
        if (tid == 0) {
            int s = base;
            #pragma unroll
            for (int w = 0; w < 8; w++) { woff[w] = s; s += wcnt[w]; }
            base = s;
        }
        __syncthreads();
        if (pred) {
            int pos = woff[wid] + __popc(m & ((1u << lane) - 1u));
            g_gene_idx[p * GENES + pos] = g;
        }
        __syncthreads();
    }
    if (tid == 0) g_gene_cnt[p] = base;
}

// ---------------- kernel 2: gate GEMM (split-K, fp32) ----------------
// x[256,4000] @ w[4000,128] -> partial[split][256][128]
__global__ void gate_gemm_kernel(const float* __restrict__ x,
                                 const float* __restrict__ w) {
    __shared__ float As[KB][64];
    __shared__ float Bs[KB][GHID];
    int b0 = blockIdx.x * 64;
    int k0 = blockIdx.y * KC;
    int t = threadIdx.x;
    int rgrp = t >> 5;   // 0..7  -> rows rgrp*8 .. +7
    int cgrp = t & 31;   // 0..31 -> cols cgrp*4 .. +3

    float acc[8][4];
    #pragma unroll
    for (int i = 0; i < 8; i++)
        #pragma unroll
        for (int j = 0; j < 4; j++) acc[i][j] = 0.0f;

    for (int kb = 0; kb < KC; kb += KB) {
        int kbase = k0 + kb;
        // load A tile (64 x 16), transposed into As[k][row]
        {
            int r = t >> 2;
            int kq = (t & 3) * 4;
            float4 av = *reinterpret_cast<const float4*>(
                x + (size_t)(b0 + r) * GENES + kbase + kq);
            As[kq + 0][r] = av.x; As[kq + 1][r] = av.y;
            As[kq + 2][r] = av.z; As[kq + 3][r] = av.w;
        }
        // load B tile (16 x 128)
        #pragma unroll
        for (int i = 0; i < 2; i++) {
            int f = t + i * 256;
            int kk = f >> 5;
            int c = (f & 31) * 4;
            *reinterpret_cast<float4*>(&Bs[kk][c]) =
                *reinterpret_cast<const float4*>(w + (size_t)(kbase + kk) * GHID + c);
        }
        __syncthreads();
        #pragma unroll
        for (int kk = 0; kk < KB; kk++) {
            float4 b4 = *reinterpret_cast<const float4*>(&Bs[kk][cgrp * 4]);
            float4 a0 = *reinterpret_cast<const float4*>(&As[kk][rgrp * 8]);
            float4 a1 = *reinterpret_cast<const float4*>(&As[kk][rgrp * 8 + 4]);
            float av[8] = {a0.x, a0.y, a0.z, a0.w, a1.x, a1.y, a1.z, a1.w};
            float bv[4] = {b4.x, b4.y, b4.z, b4.w};
            #pragma unroll
            for (int i = 0; i < 8; i++)
                #pragma unroll
                for (int j = 0; j < 4; j++)
                    acc[i][j] = fmaf(av[i], bv[j], acc[i][j]);
        }
        __syncthreads();
    }
    float* out = g_partial + (size_t)blockIdx.y * (BATCH * GHID);
    #pragma unroll
    for (int i = 0; i < 8; i++) {
        float4 v = make_float4(acc[i][0], acc[i][1], acc[i][2], acc[i][3]);
        *reinterpret_cast<float4*>(
            out + (size_t)(b0 + rgrp * 8 + i) * GHID + cgrp * 4) = v;
    }
}

// ---------------- kernel 3: deterministic split reduce + bias + relu ----------------
__global__ void gate_reduce_relu(const float* __restrict__ gb1) {
    int idx = blockIdx.x * blockDim.x + threadIdx.x;   // 0..32767
    float s = 0.0f;
    #pragma unroll
    for (int sp = 0; sp < KSPLIT; sp++)
        s += g_partial[(size_t)sp * (BATCH * GHID) + idx];
    s += gb1[idx & (GHID - 1)];
    g_hidden[idx] = fmaxf(s, 0.0f);
}

// ---------------- kernel 4: gate layer 2 ----------------
__global__ void gate_layer2(const float* __restrict__ w2,
                            const float* __restrict__ b2g) {
    __shared__ float hid[GHID];
    int b = blockIdx.x;
    int p = threadIdx.x;
    hid[p] = g_hidden[b * GHID + p];
    __syncthreads();
    float s = b2g[p];
    #pragma unroll 8
    for (int k = 0; k < GHID; k++)
        s = fmaf(hid[k], __ldg(w2 + (size_t)k * PATH + p), s);
    g_logits[b * PATH + p] = s;
}

// ---------------- kernel 5: per-row top-3 + sigmoid + scatter + pathway lists --------
__global__ void topk_kernel(float* __restrict__ out_gw) {
    int warp = threadIdx.x >> 5;
    int lane = threadIdx.x & 31;
    int b = blockIdx.x * 8 + warp;

    float v[4];
    #pragma unroll
    for (int q = 0; q < 4; q++) v[q] = g_logits[b * PATH + lane + q * 32];

    float keepv[TOPK];
    int keepi[TOPK];
    #pragma unroll
    for (int k = 0; k < TOPK; k++) {
        float bv = -1e30f; int bi = 0x7fffffff;
        #pragma unroll
        for (int q = 0; q < 4; q++) {
            int idq = lane + q * 32;
            if (v[q] > bv || (v[q] == bv && idq < bi)) { bv = v[q]; bi = idq; }
        }
        #pragma unroll
        for (int off = 16; off; off >>= 1) {
            float ov = __shfl_xor_sync(0xffffffffu, bv, off);
            int oi = __shfl_xor_sync(0xffffffffu, bi, off);
            if (ov > bv || (ov == bv && oi < bi)) { bv = ov; bi = oi; }
        }
        keepv[k] = bv; keepi[k] = bi;
        #pragma unroll
        for (int q = 0; q < 4; q++)
            if (lane + q * 32 == bi) v[q] = -1e30f;
    }
    // gate_weights output row (zeros + sigmoid(topk))
    #pragma unroll
    for (int q = 0; q < 4; q++) {
        int idq = lane + q * 32;
        float val = 0.0f;
        #pragma unroll
        for (int k = 0; k < TOPK; k++)
            if (keepi[k] == idq) val = 1.0f / (1.0f + expf(-keepv[k]));
        out_gw[(size_t)b * PATH + idq] = val;
    }
    if (lane == 0) {
        #pragma unroll
        for (int k = 0; k < TOPK; k++) {
            int p = keepi[k];
            float wgt = 1.0f / (1.0f + expf(-keepv[k]));
            int j = atomicAdd(&g_path_cnt[p], 1);
            g_path_ent[p * BATCH + j] = (b << 2) | k;
            g_path_wt[p * BATCH + j] = wgt;
        }
    }
}

// ---------------- kernel 6: sparse experts ----------------
// one block per pathway; threads = 64 H x 4 sample-slots
__global__ void expert_kernel(const float* __restrict__ x_rna,
                              const float* __restrict__ x_cnv,
                              const float* __restrict__ x_met,
                              const float* __restrict__ W1,
                              const float* __restrict__ b1,
                              const float* __restrict__ bn_gamma,
                              const float* __restrict__ bn_beta,
                              const float* __restrict__ bn_mean,
                              const float* __restrict__ bn_var,
                              const float* __restrict__ W2,
                              const float* __restrict__ b2) {
    int p = blockIdx.x;
    int cnt = g_path_cnt[p];
    if (cnt == 0) return;
    int ng = g_gene_cnt[p];
    int hh = threadIdx.x & 63;
    int sg = threadIdx.x >> 6;   // 0..3

    __shared__ float hs[4][HDIM];
    const int* glist = g_gene_idx + p * GENES;
    const float* W1p = W1 + (size_t)p * DDIM * HDIM;

    // per-h BN params (loaded once)
    float bias1 = b1[p * HDIM + hh];
    float mean  = bn_mean[p * HDIM + hh];
    float scale = bn_gamma[p * HDIM + hh] * rsqrtf(bn_var[p * HDIM + hh] + BNEPS);
    float beta  = bn_beta[p * HDIM + hh];

    for (int t0 = 0; t0 < cnt; t0 += 4) {
        int si = t0 + sg;
        bool active = si < cnt;
        int ent = g_path_ent[p * BATCH + (active ? si : (cnt - 1))];
        int b = ent >> 2;
        const float* xr = x_rna + (size_t)b * GENES;
        const float* xc = x_cnv + (size_t)b * GENES;
        const float* xm = x_met + (size_t)b * GENES;

        float acc = 0.0f;
        for (int i = 0; i < ng; i++) {
            int g = glist[i];
            float w0 = __ldg(W1p + (size_t)g * HDIM + hh);
            float w1 = __ldg(W1p + (size_t)(GENES + g) * HDIM + hh);
            float w2v = __ldg(W1p + (size_t)(2 * GENES + g) * HDIM + hh);
            float x0 = __ldg(xr + g);
            float x1 = __ldg(xc + g);
            float x2 = __ldg(xm + g);
            acc = fmaf(w0, x0, acc);
            acc = fmaf(w1, x1, acc);
            acc = fmaf(w2v, x2, acc);
        }
        float hval = (acc + bias1 - mean) * scale + beta;
        hval = fmaxf(hval, 0.0f);
        hs[sg][hh] = hval;
        __syncthreads();
        if (hh < ODIM && active) {
            int o = hh;
            float sum = 0.0f;
            #pragma unroll 8
            for (int h2 = 0; h2 < HDIM; h2++)
                sum = fmaf(hs[sg][h2], __ldg(W2 + ((size_t)p * HDIM + h2) * ODIM + o), sum);
            sum += b2[p * ODIM + o];
            float wgt = g_path_wt[p * BATCH + si];
            int k = ent & 3;
            g_contrib[((size_t)b * TOPK + k) * ODIM + o] = sum * wgt;
        }
        __syncthreads();
    }
}

// ---------------- kernel 7: classifier ----------------
__global__ void classifier_kernel(const float* __restrict__ cw1,
                                  const float* __restrict__ cb1,
                                  const float* __restrict__ cw2,
                                  const float* __restrict__ cb2,
                                  float* __restrict__ out_logits) {
    int b = threadIdx.x;   // one block of 256
    float feat[ODIM];
    #pragma unroll
    for (int o = 0; o < ODIM; o++)
        feat[o] = g_contrib[((size_t)b * TOPK + 0) * ODIM + o]
                + g_contrib[((size_t)b * TOPK + 1) * ODIM + o]
                + g_contrib[((size_t)b * TOPK + 2) * ODIM + o];
    float h8[CHID];
    #pragma unroll
    for (int c = 0; c < CHID; c++) {
        float s = cb1[c];
        #pragma unroll
        for (int o = 0; o < ODIM; o++)
            s = fmaf(feat[o], __ldg(cw1 + o * CHID + c), s);
        h8[c] = fmaxf(s, 0.0f);
    }
    #pragma unroll
    for (int c5 = 0; c5 < NCLS; c5++) {
        float s = cb2[c5];
        #pragma unroll
        for (int c = 0; c < CHID; c++)
            s = fmaf(h8[c], __ldg(cw2 + c * NCLS + c5), s);
        out_logits[(size_t)b * NCLS + c5] = s;
    }
}

// ---------------- launch ----------------
extern "C" void kernel_launch(void* const* d_in, const int* in_sizes, int n_in,
                              void* d_out, int out_size) {
    const float* x_rna    = (const float*)d_in[0];
    const float* x_cnv    = (const float*)d_in[1];
    const float* x_met    = (const float*)d_in[2];
    const float* gene_mask= (const float*)d_in[3];
    const float* gate_w1  = (const float*)d_in[4];
    const float* gate_b1  = (const float*)d_in[5];
    const float* gate_w2  = (const float*)d_in[6];
    const float* gate_b2  = (const float*)d_in[7];
    const float* W1       = (const float*)d_in[8];
    const float* b1       = (const float*)d_in[9];
    const float* bn_gamma = (const float*)d_in[10];
    const float* bn_beta  = (const float*)d_in[11];
    const float* bn_mean  = (const float*)d_in[12];
    const float* bn_var   = (const float*)d_in[13];
    const float* W2       = (const float*)d_in[14];
    const float* b2       = (const float*)d_in[15];
    const float* cls_w1   = (const float*)d_in[16];
    const float* cls_b1   = (const float*)d_in[17];
    const float* cls_w2   = (const float*)d_in[18];
    const float* cls_b2   = (const float*)d_in[19];
    float* out = (float*)d_out;
    // output layout: logits [256*5] then gate_weights [256*128]
    float* out_logits = out;
    float* out_gw = out + BATCH * NCLS;

    gene_list_kernel<<<PATH, 256>>>(gene_mask);
    gate_gemm_kernel<<<dim3(BATCH / 64, KSPLIT), 256>>>(x_rna, gate_w1);
    gate_reduce_relu<<<(BATCH * GHID) / 256, 256>>>(gate_b1);
    gate_layer2<<<BATCH, GHID>>>(gate_w2, gate_b2);
    topk_kernel<<<BATCH / 8, 256>>>(out_gw);
    expert_kernel<<<PATH, 256>>>(x_rna, x_cnv, x_met, W1, b1,
                                 bn_gamma, bn_beta, bn_mean, bn_var, W2, b2);
    classifier_kernel<<<1, BATCH>>>(cls_w1, cls_b1, cls_w2, cls_b2, out_logits);
}

// round 2
// speedup vs baseline: 30.5496x; 30.5496x over previous
#include <cuda_runtime.h>
#include <cuda_bf16.h>
#include <math.h>

// ---------------- problem constants ----------------
#define BATCH 256
#define GENES 4000
#define PATH  128      // P
#define OMICS 3
#define DDIM  (OMICS * GENES)   // 12000
#define HDIM  64
#define ODIM  16
#define GHID  128      // gate hidden
#define CHID  8
#define NCLS  5
#define TOPK  3
#define BNEPS 1e-5f
#define NENT  (BATCH * TOPK)    // 768 expert work items

// gate GEMM split-K config
#define KSPLIT 25
#define KC     160     // 25*160 = 4000
#define KB     16

// ---------------- device scratch (no allocations allowed) ----------------
__device__ float g_partial[KSPLIT * BATCH * GHID];   // split-K partials
__device__ float g_hidden[BATCH * GHID];
__device__ float g_logits[BATCH * PATH];
__device__ int   g_gene_idx[PATH * GENES];
__device__ int   g_gene_cnt[PATH];
__device__ int   g_entry[NENT];                      // pathway id per (b,k)
__device__ float g_wt[NENT];                         // sigmoid weight per (b,k)
__device__ float g_contrib[NENT * ODIM];

// ---------------- kernel 1: ordered gene-list compaction per pathway ----------------
__global__ void gene_list_kernel(const float* __restrict__ gene_mask) {
    int p = blockIdx.x;
    int tid = threadIdx.x;
    int wid = tid >> 5, lane = tid & 31;
    __shared__ int base;
    __shared__ int wcnt[8];
    __shared__ int woff[8];
    if (tid == 0) base = 0;
    __syncthreads();
    for (int g0 = 0; g0 < GENES; g0 += 256) {
        int g = g0 + tid;
        bool pred = (g < GENES) && (gene_mask[(size_t)g * PATH + p] != 0.0f);
        unsigned m = __ballot_sync(0xffffffffu, pred);
        if (lane == 0) wcnt[wid] = __popc(m);
        __syncthreads();
        if (tid == 0) {
            int s = base;
            #pragma unroll
            for (int w = 0; w < 8; w++) { woff[w] = s; s += wcnt[w]; }
            base = s;
        }
        __syncthreads();
        if (pred) {
            int pos = woff[wid] + __popc(m & ((1u << lane) - 1u));
            g_gene_idx[p * GENES + pos] = g;
        }
        __syncthreads();
    }
    if (tid == 0) g_gene_cnt[p] = base;
}

// ---------------- kernel 2: gate GEMM (split-K, fp32) ----------------
// x[256,4000] @ w[4000,128] -> partial[split][256][128]
__global__ void gate_gemm_kernel(const float* __restrict__ x,
                                 const float* __restrict__ w) {
    __shared__ float As[KB][64];
    __shared__ float Bs[KB][GHID];
    int b0 = blockIdx.x * 64;
    int k0 = blockIdx.y * KC;
    int t = threadIdx.x;
    int rgrp = t >> 5;   // 0..7  -> rows rgrp*8 .. +7
    int cgrp = t & 31;   // 0..31 -> cols cgrp*4 .. +3

    float acc[8][4];
    #pragma unroll
    for (int i = 0; i < 8; i++)
        #pragma unroll
        for (int j = 0; j < 4; j++) acc[i][j] = 0.0f;

    for (int kb = 0; kb < KC; kb += KB) {
        int kbase = k0 + kb;
        // load A tile (64 x 16), transposed into As[k][row]
        {
            int r = t >> 2;
            int kq = (t & 3) * 4;
            float4 av = *reinterpret_cast<const float4*>(
                x + (size_t)(b0 + r) * GENES + kbase + kq);
            As[kq + 0][r] = av.x; As[kq + 1][r] = av.y;
            As[kq + 2][r] = av.z; As[kq + 3][r] = av.w;
        }
        // load B tile (16 x 128)
        #pragma unroll
        for (int i = 0; i < 2; i++) {
            int f = t + i * 256;
            int kk = f >> 5;
            int c = (f & 31) * 4;
            *reinterpret_cast<float4*>(&Bs[kk][c]) =
                *reinterpret_cast<const float4*>(w + (size_t)(kbase + kk) * GHID + c);
        }
        __syncthreads();
        #pragma unroll
        for (int kk = 0; kk < KB; kk++) {
            float4 b4 = *reinterpret_cast<const float4*>(&Bs[kk][cgrp * 4]);
            float4 a0 = *reinterpret_cast<const float4*>(&As[kk][rgrp * 8]);
            float4 a1 = *reinterpret_cast<const float4*>(&As[kk][rgrp * 8 + 4]);
            float av[8] = {a0.x, a0.y, a0.z, a0.w, a1.x, a1.y, a1.z, a1.w};
            float bv[4] = {b4.x, b4.y, b4.z, b4.w};
            #pragma unroll
            for (int i = 0; i < 8; i++)
                #pragma unroll
                for (int j = 0; j < 4; j++)
                    acc[i][j] = fmaf(av[i], bv[j], acc[i][j]);
        }
        __syncthreads();
    }
    float* out = g_partial + (size_t)blockIdx.y * (BATCH * GHID);
    #pragma unroll
    for (int i = 0; i < 8; i++) {
        float4 v = make_float4(acc[i][0], acc[i][1], acc[i][2], acc[i][3]);
        *reinterpret_cast<float4*>(
            out + (size_t)(b0 + rgrp * 8 + i) * GHID + cgrp * 4) = v;
    }
}

// ---------------- kernel 3: deterministic split reduce + bias + relu ----------------
__global__ void gate_reduce_relu(const float* __restrict__ gb1) {
    int idx = blockIdx.x * blockDim.x + threadIdx.x;   // 0..32767
    float s = 0.0f;
    #pragma unroll
    for (int sp = 0; sp < KSPLIT; sp++)
        s += g_partial[(size_t)sp * (BATCH * GHID) + idx];
    s += gb1[idx & (GHID - 1)];
    g_hidden[idx] = fmaxf(s, 0.0f);
}

// ---------------- kernel 4: gate layer 2 (8 samples per block) ----------------
__global__ void gate_layer2(const float* __restrict__ w2,
                            const float* __restrict__ b2g) {
    __shared__ float hid[8][GHID];
    int b0 = blockIdx.x * 8;
    int p = threadIdx.x;      // 0..127
    #pragma unroll
    for (int r = 0; r < 8; r++)
        hid[r][p] = g_hidden[(size_t)(b0 + r) * GHID + p];
    __syncthreads();
    float bias = b2g[p];
    float s[8];
    #pragma unroll
    for (int r = 0; r < 8; r++) s[r] = bias;
    #pragma unroll 4
    for (int k = 0; k < GHID; k++) {
        float wv = __ldg(w2 + (size_t)k * PATH + p);
        #pragma unroll
        for (int r = 0; r < 8; r++)
            s[r] = fmaf(hid[r][k], wv, s[r]);
    }
    #pragma unroll
    for (int r = 0; r < 8; r++)
        g_logits[(size_t)(b0 + r) * PATH + p] = s[r];
}

// ---------------- kernel 5: per-row top-3 + sigmoid + scatter (flat list) --------
__global__ void topk_kernel(float* __restrict__ out_gw) {
    int warp = threadIdx.x >> 5;
    int lane = threadIdx.x & 31;
    int b = blockIdx.x * 8 + warp;

    float v[4];
    #pragma unroll
    for (int q = 0; q < 4; q++) v[q] = g_logits[b * PATH + lane + q * 32];

    float keepv[TOPK];
    int keepi[TOPK];
    #pragma unroll
    for (int k = 0; k < TOPK; k++) {
        float bv = -1e30f; int bi = 0x7fffffff;
        #pragma unroll
        for (int q = 0; q < 4; q++) {
            int idq = lane + q * 32;
            if (v[q] > bv || (v[q] == bv && idq < bi)) { bv = v[q]; bi = idq; }
        }
        #pragma unroll
        for (int off = 16; off; off >>= 1) {
            float ov = __shfl_xor_sync(0xffffffffu, bv, off);
            int oi = __shfl_xor_sync(0xffffffffu, bi, off);
            if (ov > bv || (ov == bv && oi < bi)) { bv = ov; bi = oi; }
        }
        keepv[k] = bv; keepi[k] = bi;
        #pragma unroll
        for (int q = 0; q < 4; q++)
            if (lane + q * 32 == bi) v[q] = -1e30f;
    }
    // gate_weights output row (zeros + sigmoid(topk))
    #pragma unroll
    for (int q = 0; q < 4; q++) {
        int idq = lane + q * 32;
        float val = 0.0f;
        #pragma unroll
        for (int k = 0; k < TOPK; k++)
            if (keepi[k] == idq) val = 1.0f / (1.0f + expf(-keepv[k]));
        out_gw[(size_t)b * PATH + idq] = val;
    }
    if (lane < TOPK) {
        int k = lane;
        g_entry[b * TOPK + k] = keepi[k];
        g_wt[b * TOPK + k] = 1.0f / (1.0f + expf(-keepv[k]));
    }
}

// ---------------- kernel 6: sparse experts, one block per (b,p) entry ----------------
// 768 blocks x 256 threads. Thread = (hh in 0..63, gene-chunk cg in 0..3).
__global__ void __launch_bounds__(256, 4)
expert_kernel(const float* __restrict__ x_rna,
              const float* __restrict__ x_cnv,
              const float* __restrict__ x_met,
              const float* __restrict__ W1,
              const float* __restrict__ b1,
              const float* __restrict__ bn_gamma,
              const float* __restrict__ bn_beta,
              const float* __restrict__ bn_mean,
              const float* __restrict__ bn_var,
              const float* __restrict__ W2,
              const float* __restrict__ b2) {
    int e = blockIdx.x;           // 0..767
    int b = e / TOPK;
    int p = g_entry[e];
    int ng = g_gene_cnt[p];
    int hh = threadIdx.x & 63;
    int cg = threadIdx.x >> 6;    // 0..3

    const int* glist = g_gene_idx + p * GENES;
    const float* W1p = W1 + (size_t)p * DDIM * HDIM;
    const float* xr = x_rna + (size_t)b * GENES;
    const float* xc = x_cnv + (size_t)b * GENES;
    const float* xm = x_met + (size_t)b * GENES;

    float acc = 0.0f;
    // strided gene loop: chunk cg takes i = cg, cg+4, ...
    int i = cg;
    for (; i + 8 <= ng; i += 8) {
        int ga = glist[i];
        int gb = glist[i + 4];
        float xa0 = __ldg(xr + ga), xa1 = __ldg(xc + ga), xa2 = __ldg(xm + ga);
        float xb0 = __ldg(xr + gb), xb1 = __ldg(xc + gb), xb2 = __ldg(xm + gb);
        float wa0 = __ldg(W1p + (size_t)ga * HDIM + hh);
        float wa1 = __ldg(W1p + (size_t)(GENES + ga) * HDIM + hh);
        float wa2 = __ldg(W1p + (size_t)(2 * GENES + ga) * HDIM + hh);
        float wb0 = __ldg(W1p + (size_t)gb * HDIM + hh);
        float wb1 = __ldg(W1p + (size_t)(GENES + gb) * HDIM + hh);
        float wb2 = __ldg(W1p + (size_t)(2 * GENES + gb) * HDIM + hh);
        acc = fmaf(wa0, xa0, acc);
        acc = fmaf(wa1, xa1, acc);
        acc = fmaf(wa2, xa2, acc);
        acc = fmaf(wb0, xb0, acc);
        acc = fmaf(wb1, xb1, acc);
        acc = fmaf(wb2, xb2, acc);
    }
    for (; i < ng; i += 4) {
        int g = glist[i];
        float w0 = __ldg(W1p + (size_t)g * HDIM + hh);
        float w1v = __ldg(W1p + (size_t)(GENES + g) * HDIM + hh);
        float w2v = __ldg(W1p + (size_t)(2 * GENES + g) * HDIM + hh);
        acc = fmaf(w0, __ldg(xr + g), acc);
        acc = fmaf(w1v, __ldg(xc + g), acc);
        acc = fmaf(w2v, __ldg(xm + g), acc);
    }

    __shared__ float part[4][HDIM];
    __shared__ float hsm[HDIM];
    part[cg][hh] = acc;
    __syncthreads();
    if (cg == 0) {
        float a = part[0][hh] + part[1][hh] + part[2][hh] + part[3][hh];
        a += b1[p * HDIM + hh];
        float scale = bn_gamma[p * HDIM + hh] * rsqrtf(bn_var[p * HDIM + hh] + BNEPS);
        a = (a - bn_mean[p * HDIM + hh]) * scale + bn_beta[p * HDIM + hh];
        hsm[hh] = fmaxf(a, 0.0f);
    }
    __syncthreads();
    // W2: 64x16 on warp 0 (16 threads, each loops 64)
    if (threadIdx.x < ODIM) {
        int o = threadIdx.x;
        const float* W2p = W2 + (size_t)p * HDIM * ODIM;
        float s = 0.0f;
        #pragma unroll 8
        for (int h2 = 0; h2 < HDIM; h2++)
            s = fmaf(hsm[h2], __ldg(W2p + h2 * ODIM + o), s);
        s += b2[p * ODIM + o];
        g_contrib[(size_t)e * ODIM + o] = s * g_wt[e];
    }
}

// ---------------- kernel 7: classifier ----------------
__global__ void classifier_kernel(const float* __restrict__ cw1,
                                  const float* __restrict__ cb1,
                                  const float* __restrict__ cw2,
                                  const float* __restrict__ cb2,
                                  float* __restrict__ out_logits) {
    int b = threadIdx.x;   // one block of 256
    float feat[ODIM];
    #pragma unroll
    for (int o = 0; o < ODIM; o++)
        feat[o] = g_contrib[((size_t)b * TOPK + 0) * ODIM + o]
                + g_contrib[((size_t)b * TOPK + 1) * ODIM + o]
                + g_contrib[((size_t)b * TOPK + 2) * ODIM + o];
    float h8[CHID];
    #pragma unroll
    for (int c = 0; c < CHID; c++) {
        float s = cb1[c];
        #pragma unroll
        for (int o = 0; o < ODIM; o++)
            s = fmaf(feat[o], __ldg(cw1 + o * CHID + c), s);
        h8[c] = fmaxf(s, 0.0f);
    }
    #pragma unroll
    for (int c5 = 0; c5 < NCLS; c5++) {
        float s = cb2[c5];
        #pragma unroll
        for (int c = 0; c < CHID; c++)
            s = fmaf(h8[c], __ldg(cw2 + c * NCLS + c5), s);
        out_logits[(size_t)b * NCLS + c5] = s;
    }
}

// ---------------- launch ----------------
extern "C" void kernel_launch(void* const* d_in, const int* in_sizes, int n_in,
                              void* d_out, int out_size) {
    const float* x_rna    = (const float*)d_in[0];
    const float* x_cnv    = (const float*)d_in[1];
    const float* x_met    = (const float*)d_in[2];
    const float* gene_mask= (const float*)d_in[3];
    const float* gate_w1  = (const float*)d_in[4];
    const float* gate_b1  = (const float*)d_in[5];
    const float* gate_w2  = (const float*)d_in[6];
    const float* gate_b2  = (const float*)d_in[7];
    const float* W1       = (const float*)d_in[8];
    const float* b1       = (const float*)d_in[9];
    const float* bn_gamma = (const float*)d_in[10];
    const float* bn_beta  = (const float*)d_in[11];
    const float* bn_mean  = (const float*)d_in[12];
    const float* bn_var   = (const float*)d_in[13];
    const float* W2       = (const float*)d_in[14];
    const float* b2       = (const float*)d_in[15];
    const float* cls_w1   = (const float*)d_in[16];
    const float* cls_b1   = (const float*)d_in[17];
    const float* cls_w2   = (const float*)d_in[18];
    const float* cls_b2   = (const float*)d_in[19];
    float* out = (float*)d_out;
    // output layout: logits [256*5] then gate_weights [256*128]
    float* out_logits = out;
    float* out_gw = out + BATCH * NCLS;

    gene_list_kernel<<<PATH, 256>>>(gene_mask);
    gate_gemm_kernel<<<dim3(BATCH / 64, KSPLIT), 256>>>(x_rna, gate_w1);
    gate_reduce_relu<<<(BATCH * GHID) / 256, 256>>>(gate_b1);
    gate_layer2<<<BATCH / 8, GHID>>>(gate_w2, gate_b2);
    topk_kernel<<<BATCH / 8, 256>>>(out_gw);
    expert_kernel<<<NENT, 256>>>(x_rna, x_cnv, x_met, W1, b1,
                                 bn_gamma, bn_beta, bn_mean, bn_var, W2, b2);
    classifier_kernel<<<1, BATCH>>>(cls_w1, cls_b1, cls_w2, cls_b2, out_logits);
}

// round 5
// speedup vs baseline: 38.3519x; 1.2554x over previous
#include <cuda_runtime.h>
#include <cuda_bf16.h>
#include <math.h>

// ---------------- problem constants ----------------
#define BATCH 256
#define GENES 4000
#define PATH  128      // P
#define OMICS 3
#define DDIM  (OMICS * GENES)   // 12000
#define HDIM  64
#define ODIM  16
#define GHID  128      // gate hidden
#define CHID  8
#define NCLS  5
#define TOPK  3
#define BNEPS 1e-5f
#define NENT  (BATCH * TOPK)    // 768 expert work items
#define MAXTILE 288             // max sum of ceil(cnt_p/4) = (768+3*128)/4

// gate GEMM split-K config
#define KSPLIT 50
#define KC     80     // 50*80 = 4000
#define KB     16

// ---------------- device scratch (no allocations allowed) ----------------
__device__ float g_partial[KSPLIT * BATCH * GHID];   // split-K partials
__device__ int   g_gene_idx[PATH * GENES];
__device__ int   g_gene_cnt[PATH];
__device__ int   g_entry[NENT];                      // pathway id per (b,k)
__device__ float g_wt[NENT];                         // sigmoid weight per (b,k)
__device__ int   g_sorted[NENT];                     // entry ids sorted by pathway
__device__ int   g_tile_p[MAXTILE];
__device__ int   g_tile_s0[MAXTILE];
__device__ int   g_tile_n[MAXTILE];
__device__ int   g_ntiles;
__device__ float g_contrib[NENT * ODIM];

// ---------------- kernel 1: ordered gene-list compaction per pathway ----------------
__global__ void gene_list_kernel(const float* __restrict__ gene_mask) {
    int p = blockIdx.x;
    int tid = threadIdx.x;
    int wid = tid >> 5, lane = tid & 31;
    __shared__ int base;
    __shared__ int wcnt[8];
    __shared__ int woff[8];
    if (tid == 0) base = 0;
    __syncthreads();
    for (int g0 = 0; g0 < GENES; g0 += 256) {
        int g = g0 + tid;
        bool pred = (g < GENES) && (gene_mask[(size_t)g * PATH + p] != 0.0f);
        unsigned m = __ballot_sync(0xffffffffu, pred);
        if (lane == 0) wcnt[wid] = __popc(m);
        __syncthreads();
        if (tid == 0) {
            int s = base;
            #pragma unroll
            for (int w = 0; w < 8; w++) { woff[w] = s; s += wcnt[w]; }
            base = s;
        }
        __syncthreads();
        if (pred) {
            int pos = woff[wid] + __popc(m & ((1u << lane) - 1u));
            g_gene_idx[p * GENES + pos] = g;
        }
        __syncthreads();
    }
    if (tid == 0) g_gene_cnt[p] = base;
}

// ---------------- kernel 2: gate GEMM (split-K, fp32) ----------------
// x[256,4000] @ w[4000,128] -> partial[split][256][128]
__global__ void gate_gemm_kernel(const float* __restrict__ x,
                                 const float* __restrict__ w) {
    __shared__ float As[KB][64];
    __shared__ float Bs[KB][GHID];
    int b0 = blockIdx.x * 64;
    int k0 = blockIdx.y * KC;
    int t = threadIdx.x;
    int rgrp = t >> 5;   // 0..7  -> rows rgrp*8 .. +7
    int cgrp = t & 31;   // 0..31 -> cols cgrp*4 .. +3

    float acc[8][4];
    #pragma unroll
    for (int i = 0; i < 8; i++)
        #pragma unroll
        for (int j = 0; j < 4; j++) acc[i][j] = 0.0f;

    for (int kb = 0; kb < KC; kb += KB) {
        int kbase = k0 + kb;
        // load A tile (64 x 16), transposed into As[k][row]
        {
            int r = t >> 2;
            int kq = (t & 3) * 4;
            float4 av = *reinterpret_cast<const float4*>(
                x + (size_t)(b0 + r) * GENES + kbase + kq);
            As[kq + 0][r] = av.x; As[kq + 1][r] = av.y;
            As[kq + 2][r] = av.z; As[kq + 3][r] = av.w;
        }
        // load B tile (16 x 128)
        #pragma unroll
        for (int i = 0; i < 2; i++) {
            int f = t + i * 256;
            int kk = f >> 5;
            int c = (f & 31) * 4;
            *reinterpret_cast<float4*>(&Bs[kk][c]) =
                *reinterpret_cast<const float4*>(w + (size_t)(kbase + kk) * GHID + c);
        }
        __syncthreads();
        #pragma unroll
        for (int kk = 0; kk < KB; kk++) {
            float4 b4 = *reinterpret_cast<const float4*>(&Bs[kk][cgrp * 4]);
            float4 a0 = *reinterpret_cast<const float4*>(&As[kk][rgrp * 8]);
            float4 a1 = *reinterpret_cast<const float4*>(&As[kk][rgrp * 8 + 4]);
            float av[8] = {a0.x, a0.y, a0.z, a0.w, a1.x, a1.y, a1.z, a1.w};
            float bv[4] = {b4.x, b4.y, b4.z, b4.w};
            #pragma unroll
            for (int i = 0; i < 8; i++)
                #pragma unroll
                for (int j = 0; j < 4; j++)
                    acc[i][j] = fmaf(av[i], bv[j], acc[i][j]);
        }
        __syncthreads();
    }
    float* out = g_partial + (size_t)blockIdx.y * (BATCH * GHID);
    #pragma unroll
    for (int i = 0; i < 8; i++) {
        float4 v = make_float4(acc[i][0], acc[i][1], acc[i][2], acc[i][3]);
        *reinterpret_cast<float4*>(
            out + (size_t)(b0 + rgrp * 8 + i) * GHID + cgrp * 4) = v;
    }
}

// ---------------- kernel 3: fused gate finish (reduce + relu + layer2 + top3) ----
// one block per sample, 128 threads
__global__ void gate_finish(const float* __restrict__ gb1,
                            const float* __restrict__ w2,
                            const float* __restrict__ b2g,
                            float* __restrict__ out_gw) {
    __shared__ float hid[GHID];
    __shared__ float lg[PATH];
    __shared__ float sv[TOPK];
    __shared__ int   si[TOPK];
    int b = blockIdx.x;
    int p = threadIdx.x;

    // split-K reduce + bias + relu
    float s = 0.0f;
    #pragma unroll
    for (int sp = 0; sp < KSPLIT; sp++)
        s += g_partial[(size_t)sp * (BATCH * GHID) + b * GHID + p];
    s += gb1[p];
    hid[p] = fmaxf(s, 0.0f);
    __syncthreads();

    // layer 2: logit[p] = b2 + sum_k hid[k] * w2[k][p]
    float acc = b2g[p];
    #pragma unroll 8
    for (int k = 0; k < GHID; k++)
        acc = fmaf(hid[k], __ldg(w2 + (size_t)k * PATH + p), acc);
    lg[p] = acc;
    __syncthreads();

    // warp 0: top-3 over 128 values (tie-break: lower index)
    if (p < 32) {
        float v[4];
        #pragma unroll
        for (int q = 0; q < 4; q++) v[q] = lg[p + q * 32];
        #pragma unroll
        for (int k = 0; k < TOPK; k++) {
            float bv = -1e30f; int bi = 0x7fffffff;
            #pragma unroll
            for (int q = 0; q < 4; q++) {
                int idq = p + q * 32;
                if (v[q] > bv || (v[q] == bv && idq < bi)) { bv = v[q]; bi = idq; }
            }
            #pragma unroll
            for (int off = 16; off; off >>= 1) {
                float ov = __shfl_xor_sync(0xffffffffu, bv, off);
                int oi = __shfl_xor_sync(0xffffffffu, bi, off);
                if (ov > bv || (ov == bv && oi < bi)) { bv = ov; bi = oi; }
            }
            if (p == 0) { sv[k] = bv; si[k] = bi; }
            #pragma unroll
            for (int q = 0; q < 4; q++)
                if (p + q * 32 == bi) v[q] = -1e30f;
        }
    }
    __syncthreads();

    // write gate_weights row
    float val = 0.0f;
    #pragma unroll
    for (int k = 0; k < TOPK; k++)
        if (si[k] == p) val = 1.0f / (1.0f + expf(-sv[k]));
    out_gw[(size_t)b * PATH + p] = val;
    if (p < TOPK) {
        g_entry[b * TOPK + p] = si[p];
        g_wt[b * TOPK + p] = 1.0f / (1.0f + expf(-sv[p]));
    }
}

// ---------------- kernel 4: counting sort by pathway + tile list ----------------
__global__ void sort_kernel() {
    __shared__ int hist[PATH];
    __shared__ int off[PATH];
    __shared__ int toff[PATH];
    __shared__ int cur[PATH];
    int tid = threadIdx.x;
    if (tid < PATH) { hist[tid] = 0; cur[tid] = 0; }
    __syncthreads();
    for (int e = tid; e < NENT; e += 256)
        atomicAdd(&hist[g_entry[e]], 1);
    __syncthreads();
    if (tid == 0) {
        int s = 0, ts = 0;
        for (int p = 0; p < PATH; p++) {
            off[p] = s; s += hist[p];
            toff[p] = ts; ts += (hist[p] + 3) >> 2;
        }
        g_ntiles = ts;
    }
    __syncthreads();
    for (int e = tid; e < NENT; e += 256) {
        int p = g_entry[e];
        int pos = off[p] + atomicAdd(&cur[p], 1);
        g_sorted[pos] = e;
    }
    if (tid < PATH) {
        int p = tid;
        int n = hist[p];
        int nt = (n + 3) >> 2;
        for (int t = 0; t < nt; t++) {
            int idx = toff[p] + t;
            g_tile_p[idx] = p;
            g_tile_s0[idx] = off[p] + 4 * t;
            int rem = n - 4 * t;
            g_tile_n[idx] = rem < 4 ? rem : 4;
        }
    }
}

// ---------------- kernel 5: sparse experts, tiled by pathway ----------------
// block = tile (pathway p, up to 4 samples). 256 threads = 16 h4-groups x 16 gene-chunks.
#define GCHUNK 256
__global__ void __launch_bounds__(256, 4)
expert_kernel(const float* __restrict__ x_rna,
              const float* __restrict__ x_cnv,
              const float* __restrict__ x_met,
              const float* __restrict__ W1,
              const float* __restrict__ b1,
              const float* __restrict__ bn_gamma,
              const float* __restrict__ bn_beta,
              const float* __restrict__ bn_mean,
              const float* __restrict__ bn_var,
              const float* __restrict__ W2,
              const float* __restrict__ b2) {
    int t = blockIdx.x;
    if (t >= g_ntiles) return;
    int p  = g_tile_p[t];
    int s0 = g_tile_s0[t];
    int n  = g_tile_n[t];
    if (n <= 0) return;
    int ng = g_gene_cnt[p];
    int tid = threadIdx.x;
    int h4 = tid & 15;    // h columns 4*h4 .. 4*h4+3
    int cg = tid >> 4;    // gene chunk 0..15

    __shared__ float xs[GCHUNK * 16];      // [gene][omic*4 + sample], padded to 16
    __shared__ int   gs[GCHUNK];
    __shared__ float red[16 * 4 * HDIM];   // [cg][s][h]
    __shared__ float hsm[4][HDIM];
    __shared__ float w2s[HDIM * ODIM];
    __shared__ int   es[4];
    __shared__ int   bs[4];

    if (tid < 4) {
        int sl = tid < n ? tid : n - 1;
        int e = g_sorted[s0 + sl];
        es[tid] = e;
        bs[tid] = e / TOPK;
    }
    // stage W2 for this pathway
    const float* W2p = W2 + (size_t)p * HDIM * ODIM;
    for (int j = tid; j < HDIM * ODIM; j += 256) w2s[j] = W2p[j];
    __syncthreads();

    const int* glist = g_gene_idx + p * GENES;
    const float* W1p = W1 + (size_t)p * DDIM * HDIM;

    // acc[h][s]: h = 0..3 (cols 4*h4+h), s = sample 0..3
    float acc[4][4];
    #pragma unroll
    for (int i = 0; i < 4; i++)
        #pragma unroll
        for (int j = 0; j < 4; j++) acc[i][j] = 0.0f;

    int b0s = bs[0], b1s = bs[1], b2s = bs[2], b3s = bs[3];

    for (int gc0 = 0; gc0 < ng; gc0 += GCHUNK) {
        int nc = ng - gc0; if (nc > GCHUNK) nc = GCHUNK;
        // stage gene indices
        for (int i = tid; i < nc; i += 256) gs[i] = glist[gc0 + i];
        // stage x values: xs[i*16 + omic*4 + s]
        for (int j = tid; j < nc * 16; j += 256) {
            int i = j >> 4, r = j & 15;
            if (r < 12) {
                int omic = r >> 2, s = r & 3;
                int g = glist[gc0 + i];
                int bsmp = (s == 0) ? b0s : (s == 1) ? b1s : (s == 2) ? b2s : b3s;
                const float* xp = (omic == 0) ? x_rna : (omic == 1) ? x_cnv : x_met;
                xs[j] = xp[(size_t)bsmp * GENES + g];
            }
        }
        __syncthreads();
        // compute: chunk cg takes genes i = cg, cg+16, ...
        for (int i = cg; i < nc; i += 16) {
            int g = gs[i];
            const float* wrow = W1p + (size_t)g * HDIM + 4 * h4;
            #pragma unroll
            for (int omic = 0; omic < OMICS; omic++) {
                float4 w4 = *reinterpret_cast<const float4*>(
                    wrow + (size_t)omic * GENES * HDIM);
                float4 x4 = *reinterpret_cast<const float4*>(
                    &xs[i * 16 + omic * 4]);   // samples 0..3
                float xv[4] = {x4.x, x4.y, x4.z, x4.w};
                float wv[4] = {w4.x, w4.y, w4.z, w4.w};
                #pragma unroll
                for (int h = 0; h < 4; h++)
                    #pragma unroll
                    for (int s = 0; s < 4; s++)
                        acc[h][s] = fmaf(wv[h], xv[s], acc[h][s]);
            }
        }
        __syncthreads();
    }

    // store partials: red[cg][s][h]
    #pragma unroll
    for (int h = 0; h < 4; h++) {
        int hh = 4 * h4 + h;
        #pragma unroll
        for (int s = 0; s < 4; s++)
            red[(cg * 4 + s) * HDIM + hh] = acc[h][s];
    }
    __syncthreads();

    // reduce over 16 chunks + BN + ReLU: thread = (s, hh)
    {
        int s = tid >> 6;       // 0..3
        int hh = tid & 63;
        float a = 0.0f;
        #pragma unroll
        for (int c = 0; c < 16; c++)
            a += red[(c * 4 + s) * HDIM + hh];
        a += b1[p * HDIM + hh];
        float scale = bn_gamma[p * HDIM + hh] * rsqrtf(bn_var[p * HDIM + hh] + BNEPS);
        a = (a - bn_mean[p * HDIM + hh]) * scale + bn_beta[p * HDIM + hh];
        hsm[s][hh] = fmaxf(a, 0.0f);
    }
    __syncthreads();

    // W2: thread = (s, o), 64 threads
    if (tid < 64) {
        int s = tid >> 4;
        int o = tid & 15;
        if (s < n) {
            float sum = 0.0f;
            #pragma unroll 8
            for (int h2 = 0; h2 < HDIM; h2++)
                sum = fmaf(hsm[s][h2], w2s[h2 * ODIM + o], sum);
            sum += b2[p * ODIM + o];
            int e = es[s];
            g_contrib[(size_t)e * ODIM + o] = sum * g_wt[e];
        }
    }
}

// ---------------- kernel 6: classifier ----------------
__global__ void classifier_kernel(const float* __restrict__ cw1,
                                  const float* __restrict__ cb1,
                                  const float* __restrict__ cw2,
                                  const float* __restrict__ cb2,
                                  float* __restrict__ out_logits) {
    int b = threadIdx.x;   // one block of 256
    float feat[ODIM];
    #pragma unroll
    for (int o = 0; o < ODIM; o++)
        feat[o] = g_contrib[((size_t)b * TOPK + 0) * ODIM + o]
                + g_contrib[((size_t)b * TOPK + 1) * ODIM + o]
                + g_contrib[((size_t)b * TOPK + 2) * ODIM + o];
    float h8[CHID];
    #pragma unroll
    for (int c = 0; c < CHID; c++) {
        float s = cb1[c];
        #pragma unroll
        for (int o = 0; o < ODIM; o++)
            s = fmaf(feat[o], __ldg(cw1 + o * CHID + c), s);
        h8[c] = fmaxf(s, 0.0f);
    }
    #pragma unroll
    for (int c5 = 0; c5 < NCLS; c5++) {
        float s = cb2[c5];
        #pragma unroll
        for (int c = 0; c < CHID; c++)
            s = fmaf(h8[c], __ldg(cw2 + c * NCLS + c5), s);
        out_logits[(size_t)b * NCLS + c5] = s;
    }
}

// ---------------- launch ----------------
extern "C" void kernel_launch(void* const* d_in, const int* in_sizes, int n_in,
                              void* d_out, int out_size) {
    const float* x_rna    = (const float*)d_in[0];
    const float* x_cnv    = (const float*)d_in[1];
    const float* x_met    = (const float*)d_in[2];
    const float* gene_mask= (const float*)d_in[3];
    const float* gate_w1  = (const float*)d_in[4];
    const float* gate_b1  = (const float*)d_in[5];
    const float* gate_w2  = (const float*)d_in[6];
    const float* gate_b2  = (const float*)d_in[7];
    const float* W1       = (const float*)d_in[8];
    const float* b1       = (const float*)d_in[9];
    const float* bn_gamma = (const float*)d_in[10];
    const float* bn_beta  = (const float*)d_in[11];
    const float* bn_mean  = (const float*)d_in[12];
    const float* bn_var   = (const float*)d_in[13];
    const float* W2       = (const float*)d_in[14];
    const float* b2       = (const float*)d_in[15];
    const float* cls_w1   = (const float*)d_in[16];
    const float* cls_b1   = (const float*)d_in[17];
    const float* cls_w2   = (const float*)d_in[18];
    const float* cls_b2   = (const float*)d_in[19];
    float* out = (float*)d_out;
    // output layout: logits [256*5] then gate_weights [256*128]
    float* out_logits = out;
    float* out_gw = out + BATCH * NCLS;

    gene_list_kernel<<<PATH, 256>>>(gene_mask);
    gate_gemm_kernel<<<dim3(BATCH / 64, KSPLIT), 256>>>(x_rna, gate_w1);
    gate_finish<<<BATCH, GHID>>>(gate_b1, gate_w2, gate_b2, out_gw);
    sort_kernel<<<1, 256>>>();
    expert_kernel<<<MAXTILE, 256>>>(x_rna, x_cnv, x_met, W1, b1,
                                    bn_gamma, bn_beta, bn_mean, bn_var, W2, b2);
    classifier_kernel<<<1, BATCH>>>(cls_w1, cls_b1, cls_w2, cls_b2, out_logits);
}